// round 11
// baseline (speedup 1.0000x reference)
#include <cuda_runtime.h>
#include <stdint.h>

#define TT 64          // num types
#define CC 128         // channels
#define TC (TT * CC)   // 8192 stat entries
#define MAXN (1 << 21) // max rows (N = 1e6 fits)
#define GH 444         // grid for sort/gather (148 SMs x 3 — all co-resident)

// ---- device scratch (no allocations allowed) ----
// INVARIANT: g_sum/g_sum2/g_typecnt/g_arrive/g_depart are ZERO at the start
// of every kernel_launch: zero-initialized at module load, and re-zeroed by
// the tail of each run (k_gather finalize / barrier self-reset).
__device__ int   g_perm[MAXN];        // rows sorted by type (8 MB)
__device__ int   g_typecnt[TT];
__device__ int   g_typestart[TT + 1];
__device__ float g_sum[TC];
__device__ float g_sum2[TC];
__device__ float g_cnt[TT];
__device__ float g_mean[TC];
__device__ float g_rstd[TC];
__device__ int   g_is64;
__device__ int   g_arrive;            // grid barrier (self-resetting)
__device__ int   g_depart;

// Self-resetting grid barrier: all GH blocks must be co-resident.
// The last departing block zeroes both counters (safe: depart==GH proves
// every block already exited the arrive-spin).
__device__ __forceinline__ void grid_barrier(int tid) {
    __syncthreads();
    __threadfence();
    if (tid == 0) {
        atomicAdd(&g_arrive, 1);
        while (*((volatile int*)&g_arrive) < GH)
            __nanosleep(32);
        int d = atomicAdd(&g_depart, 1);
        if (d == GH - 1) { g_depart = 0; g_arrive = 0; }
        __threadfence();
    }
    __syncthreads();
}

// ---------------------------------------------------------------------------
// Kernel 1: FUSED is64-detect + hist + prefix + scatter (one pass over tv).
//   Phase A: detect encoding (parallel, benign-race flag); cache this block's
//            tv chunk in smem while histogramming; publish per-type offsets.
//   Grid barrier. Phase B: local 64-wide scan of final g_typecnt; scatter
//   from the smem cache. Block 0 publishes g_typestart / g_cnt / g_is64.
// ---------------------------------------------------------------------------
__global__ void __launch_bounds__(256) k_sort(
    const void* __restrict__ tv, long long N)
{
    extern __shared__ int stv[];          // chunk cache
    __shared__ int hist[TT];              // phase A hist -> phase B srank
    __shared__ int sbase[TT];
    __shared__ int sscan[TT];
    __shared__ int scnt0[TT];
    __shared__ int myoff[TT];
    __shared__ int s_is64;

    const int tid = threadIdx.x;
    const long long chunk = (N + GH - 1) / GH;
    const long long lo = (long long)blockIdx.x * chunk;
    const long long hi = (lo + chunk < N) ? lo + chunk : N;
    const int cnt = (int)((hi > lo) ? (hi - lo) : 0);

    if (tid < TT) hist[tid] = 0;
    if (tid == 0) s_is64 = 1;
    __syncthreads();

    // int64 values 0..63 little-endian -> every odd int32 word == 0.
    {
        const int* p = (const int*)tv;
        const int lim = (N >= 256) ? 256 : (int)N;   // words safe to read
        if (tid < 128) {
            int i = 2 * tid + 1;
            if (i < lim && p[i] != 0) s_is64 = 0;    // benign race
        }
    }
    __syncthreads();
    const int is64 = s_is64;
    if (tid == 0) g_is64 = is64;                      // for k_norm

    const long long* __restrict__ tv64 = (const long long*)tv;
    const int*       __restrict__ tv32 = (const int*)tv;

    // Phase A: load chunk -> smem cache + histogram
    for (int i = tid; i < cnt; i += 256) {
        int t = is64 ? (int)tv64[lo + i] : tv32[lo + i];
        stv[i] = t;
        atomicAdd(&hist[t], 1);
    }
    __syncthreads();
    if (tid < TT)
        myoff[tid] = atomicAdd(&g_typecnt[tid], hist[tid]);

    grid_barrier(tid);

    // Phase B: local 64-wide exclusive scan of the final g_typecnt
    if (tid < TT) {
        int c = g_typecnt[tid];
        scnt0[tid] = c;
        sscan[tid] = c;
    }
    __syncthreads();
    #pragma unroll
    for (int off = 1; off < TT; off <<= 1) {
        int v = 0;
        if (tid < TT && tid >= off) v = sscan[tid - off];
        __syncthreads();
        if (tid < TT) sscan[tid] += v;
        __syncthreads();
    }
    if (tid < TT) {
        int excl = sscan[tid] - scnt0[tid];
        sbase[tid] = excl + myoff[tid];
        hist[tid] = 0;                      // reuse as srank
        if (blockIdx.x == 0) {
            g_typestart[tid] = excl;
            g_cnt[tid] = (float)scnt0[tid];
            if (tid == TT - 1) g_typestart[TT] = sscan[tid];
        }
    }
    __syncthreads();

    // Scatter from the smem cache (no second global tv read).
    for (int i = tid; i < cnt; i += 256) {
        int t = stv[i];
        int r = atomicAdd(&hist[t], 1);
        g_perm[sbase[t] + r] = (int)(lo + i);
    }
}

// ---------------------------------------------------------------------------
// Kernel 2: gather-accumulate + FUSED finalize.
//   Warp-per-row over perm (type-sorted), lane l owns channels [4l,4l+4).
//   REGISTER float4 sum/sumsq; atomic flush only at type boundaries.
//   Then grid barrier; first TC global threads finalize mean/rstd and
//   RE-ZERO g_sum/g_sum2/g_typecnt for the next replay.
//   __launch_bounds__(256,3) guarantees all 444 blocks co-resident.
// ---------------------------------------------------------------------------
#define CW 8
__global__ void __launch_bounds__(256, 3) k_gather(
    const float* __restrict__ x, long long N)
{
    __shared__ int st[TT + 1];
    const int tid  = threadIdx.x;
    const int lane = tid & 31;
    for (int i = tid; i < TT + 1; i += 256) st[i] = g_typestart[i];
    __syncthreads();

    const long long nwarps = (long long)GH * 8;
    const long long gw  = (long long)blockIdx.x * 8 + (tid >> 5);
    const long long per = (N + nwarps - 1) / nwarps;
    const long long a = gw * per;
    const long long b = (a + per < N) ? a + per : N;

    if (a < b) {   // NO early return: every thread must reach the barrier
        int t = 0;
        while (st[t + 1] <= (int)a) t++;
        int nxt = st[t + 1];

        float4 s = make_float4(0.f, 0.f, 0.f, 0.f);
        float4 q = make_float4(0.f, 0.f, 0.f, 0.f);
        const float4* __restrict__ x4 = (const float4*)x;

#define FLUSH() do {                                                      \
        if (q.x + q.y + q.z + q.w != 0.f) {                               \
            int base_ = t * CC + 4 * lane;                                \
            atomicAdd(&g_sum[base_ + 0], s.x);                            \
            atomicAdd(&g_sum[base_ + 1], s.y);                            \
            atomicAdd(&g_sum[base_ + 2], s.z);                            \
            atomicAdd(&g_sum[base_ + 3], s.w);                            \
            atomicAdd(&g_sum2[base_ + 0], q.x);                           \
            atomicAdd(&g_sum2[base_ + 1], q.y);                           \
            atomicAdd(&g_sum2[base_ + 2], q.z);                           \
            atomicAdd(&g_sum2[base_ + 3], q.w);                           \
            s = make_float4(0.f, 0.f, 0.f, 0.f);                          \
            q = make_float4(0.f, 0.f, 0.f, 0.f);                          \
        }                                                                  \
    } while (0)

        int rrA[CW];
        #pragma unroll
        for (int u = 0; u < CW; u++)
            rrA[u] = (a + u < b) ? g_perm[a + u] : 0;

        for (long long i = a; i < b; i += CW) {
            int rrB[CW];
            const long long i2 = i + CW;
            #pragma unroll
            for (int u = 0; u < CW; u++)
                rrB[u] = (i2 + u < b) ? g_perm[i2 + u] : 0;

            const int m = (int)((b - i < CW) ? (b - i) : CW);
            float4 xv[CW];
            #pragma unroll
            for (int u = 0; u < CW; u++)
                if (u < m) xv[u] = x4[(long long)rrA[u] * (CC / 4) + lane];

            #pragma unroll
            for (int u = 0; u < CW; u++) {
                if (u < m) {
                    const int idx = (int)(i + u);
                    if (idx >= nxt) {            // type boundary (rare)
                        FLUSH();
                        do { t++; } while (st[t + 1] <= idx);
                        nxt = st[t + 1];
                    }
                    s.x += xv[u].x; s.y += xv[u].y;
                    s.z += xv[u].z; s.w += xv[u].w;
                    q.x = fmaf(xv[u].x, xv[u].x, q.x);
                    q.y = fmaf(xv[u].y, xv[u].y, q.y);
                    q.z = fmaf(xv[u].z, xv[u].z, q.z);
                    q.w = fmaf(xv[u].w, xv[u].w, q.w);
                }
            }
            #pragma unroll
            for (int u = 0; u < CW; u++) rrA[u] = rrB[u];
        }
        FLUSH();
#undef FLUSH
    }

    grid_barrier(tid);   // all g_sum/g_sum2 atomics now visible

    // Finalize: mean / rstd (cnt >= 1, var >= 0, std = sqrt(var+1e-5)).
    // Then re-zero scratch so the next replay starts clean.
    const int e = blockIdx.x * 256 + tid;
    if (e < TC) {
        float cnt  = fmaxf(g_cnt[e >> 7], 1.f);
        float mean = g_sum[e] / cnt;
        float var  = fmaxf(g_sum2[e] / cnt - mean * mean, 0.f);
        g_mean[e] = mean;
        g_rstd[e] = 1.f / sqrtf(var + 1e-5f);
        g_sum[e]  = 0.f;
        g_sum2[e] = 0.f;
    }
    if (e < TT) g_typecnt[e] = 0;
}

// ---------------------------------------------------------------------------
// Kernel 3: normalize (at the HBM cap ~6.3 TB/s; proven design).
// Warp-per-row, float4 loads/stores, stats staged in shared as SEPARATE
// mean/rstd tables (conflict-free LDS.128). blockDim = 512, grid = 444.
// ---------------------------------------------------------------------------
#define NRM_U 4
__global__ void __launch_bounds__(512) k_norm(
    const float* __restrict__ x, const void* __restrict__ tv,
    float* __restrict__ out, long long N)
{
    extern __shared__ float smn[];
    float* smean = smn;        // TC
    float* srstd = smn + TC;   // TC
    const int tid = threadIdx.x;

    #pragma unroll
    for (int i = tid; i < TC; i += 512) {
        smean[i] = g_mean[i];
        srstd[i] = g_rstd[i];
    }
    __syncthreads();

    const int is64 = g_is64;
    const long long* __restrict__ tv64 = (const long long*)tv;
    const int*       __restrict__ tv32 = (const int*)tv;

    const int lane = tid & 31;
    const long long w  = (long long)blockIdx.x * 16 + (tid >> 5);
    const long long nw = (long long)gridDim.x * 16;
    const float4* __restrict__ x4 = (const float4*)x;
    float4* __restrict__ o4 = (float4*)out;

    for (long long r0 = w * NRM_U; r0 < N; r0 += nw * NRM_U) {
        float4 xv[NRM_U];
        int    ty[NRM_U];

        #pragma unroll
        for (int u = 0; u < NRM_U; u++) {
            long long r = r0 + u;
            if (r < N) {
                ty[u] = is64 ? (int)tv64[r] : tv32[r];
                xv[u] = x4[r * (CC / 4) + lane];
            } else ty[u] = -1;
        }
        #pragma unroll
        for (int u = 0; u < NRM_U; u++) {
            if (ty[u] >= 0) {
                int o = ty[u] * CC + 4 * lane;
                float4 mn = *(const float4*)&smean[o];
                float4 rs = *(const float4*)&srstd[o];
                float4 res;
                res.x = (xv[u].x - mn.x) * rs.x;
                res.y = (xv[u].y - mn.y) * rs.y;
                res.z = (xv[u].z - mn.z) * rs.z;
                res.w = (xv[u].w - mn.w) * rs.w;
                o4[(r0 + u) * (CC / 4) + lane] = res;
            }
        }
    }
}

// ---------------------------------------------------------------------------
// Launch — 3 kernels total (was 5).
// ---------------------------------------------------------------------------
extern "C" void kernel_launch(void* const* d_in, const int* in_sizes, int n_in,
                              void* d_out, int out_size)
{
    const float* x  = (const float*)d_in[0];
    const void*  tv = d_in[1];
    float* out = (float*)d_out;
    const long long N = (long long)in_sizes[1];   // rows (type_vec length)

    const long long chunk = (N + GH - 1) / GH;
    const int SORT_SMEM = (int)(chunk * sizeof(int));   // tv cache (~9 KB @ N=1e6)
    const int NRM_SMEM  = 2 * TC * (int)sizeof(float);  // 64 KB

    cudaFuncSetAttribute(k_sort, cudaFuncAttributeMaxDynamicSharedMemorySize, SORT_SMEM);
    cudaFuncSetAttribute(k_norm, cudaFuncAttributeMaxDynamicSharedMemorySize, NRM_SMEM);

    k_sort  <<<GH, 256, SORT_SMEM>>>(tv, N);
    k_gather<<<GH, 256>>>(x, N);
    k_norm  <<<444, 512, NRM_SMEM>>>(x, tv, out, N);
}

// round 12
// speedup vs baseline: 1.0060x; 1.0060x over previous
#include <cuda_runtime.h>
#include <stdint.h>

#define TT 64          // num types
#define CC 128         // channels
#define TC (TT * CC)   // 8192 stat entries
#define MAXN (1 << 21) // max rows (N = 1e6 fits)
#define GH 444         // grid for sort/gather (148 SMs x 3 — all co-resident)

// ---- device scratch (no allocations allowed) ----
// INVARIANT: g_sum/g_sum2/g_typecnt/g_arrive/g_depart are ZERO at the start
// of every kernel_launch: zero-initialized at module load, and re-zeroed by
// the tail of each run (k_gather finalize / barrier self-reset).
__device__ int   g_perm[MAXN];        // rows sorted by type (8 MB)
__device__ int   g_typecnt[TT];
__device__ int   g_typestart[TT + 1];
__device__ float g_sum[TC];
__device__ float g_sum2[TC];
__device__ float g_cnt[TT];
__device__ float g_mean[TC];
__device__ float g_rstd[TC];
__device__ int   g_is64;
__device__ int   g_arrive;            // grid barrier (self-resetting)
__device__ int   g_depart;

// Self-resetting grid barrier: all GH blocks must be co-resident.
// The last departing block zeroes both counters (safe: depart==GH proves
// every block already exited the arrive-spin).
__device__ __forceinline__ void grid_barrier(int tid) {
    __syncthreads();
    __threadfence();
    if (tid == 0) {
        atomicAdd(&g_arrive, 1);
        while (*((volatile int*)&g_arrive) < GH)
            __nanosleep(32);
        int d = atomicAdd(&g_depart, 1);
        if (d == GH - 1) { g_depart = 0; g_arrive = 0; }
        __threadfence();
    }
    __syncthreads();
}

// ---------------------------------------------------------------------------
// Kernel 1: FUSED is64-detect + hist + prefix + scatter (one pass over tv).
//   512 threads (16 warps x 3 blocks = 48 warps/SM): both phases are
//   latency-bound dependent chains, so warp count sets throughput.
//   Phase A: detect encoding; cache this block's tv chunk in smem while
//            histogramming; publish per-type block offsets.
//   Grid barrier. Phase B: local 64-wide scan of final g_typecnt; scatter
//   from the smem cache. Block 0 publishes g_typestart / g_cnt / g_is64.
// ---------------------------------------------------------------------------
#define STB 512
__global__ void __launch_bounds__(STB) k_sort(
    const void* __restrict__ tv, long long N)
{
    extern __shared__ int stv[];          // chunk cache
    __shared__ int hist[TT];              // phase A hist -> phase B srank
    __shared__ int sbase[TT];
    __shared__ int sscan[TT];
    __shared__ int scnt0[TT];
    __shared__ int myoff[TT];
    __shared__ int s_is64;

    const int tid = threadIdx.x;
    const long long chunk = (N + GH - 1) / GH;
    const long long lo = (long long)blockIdx.x * chunk;
    const long long hi = (lo + chunk < N) ? lo + chunk : N;
    const int cnt = (int)((hi > lo) ? (hi - lo) : 0);

    if (tid < TT) hist[tid] = 0;
    if (tid == 0) s_is64 = 1;
    __syncthreads();

    // int64 values 0..63 little-endian -> every odd int32 word == 0.
    {
        const int* p = (const int*)tv;
        const int lim = (N >= 256) ? 256 : (int)N;   // words safe to read
        if (tid < 128) {
            int i = 2 * tid + 1;
            if (i < lim && p[i] != 0) s_is64 = 0;    // benign race
        }
    }
    __syncthreads();
    const int is64 = s_is64;
    if (tid == 0) g_is64 = is64;                      // for k_norm

    const long long* __restrict__ tv64 = (const long long*)tv;
    const int*       __restrict__ tv32 = (const int*)tv;

    // Phase A: load chunk -> smem cache + histogram
    for (int i = tid; i < cnt; i += STB) {
        int t = is64 ? (int)tv64[lo + i] : tv32[lo + i];
        stv[i] = t;
        atomicAdd(&hist[t], 1);
    }
    __syncthreads();
    if (tid < TT)
        myoff[tid] = atomicAdd(&g_typecnt[tid], hist[tid]);

    grid_barrier(tid);

    // Phase B: local 64-wide exclusive scan of the final g_typecnt
    if (tid < TT) {
        int c = g_typecnt[tid];
        scnt0[tid] = c;
        sscan[tid] = c;
    }
    __syncthreads();
    #pragma unroll
    for (int off = 1; off < TT; off <<= 1) {
        int v = 0;
        if (tid < TT && tid >= off) v = sscan[tid - off];
        __syncthreads();
        if (tid < TT) sscan[tid] += v;
        __syncthreads();
    }
    if (tid < TT) {
        int excl = sscan[tid] - scnt0[tid];
        sbase[tid] = excl + myoff[tid];
        hist[tid] = 0;                      // reuse as srank
        if (blockIdx.x == 0) {
            g_typestart[tid] = excl;
            g_cnt[tid] = (float)scnt0[tid];
            if (tid == TT - 1) g_typestart[TT] = sscan[tid];
        }
    }
    __syncthreads();

    // Scatter from the smem cache (no second global tv read).
    for (int i = tid; i < cnt; i += STB) {
        int t = stv[i];
        int r = atomicAdd(&hist[t], 1);
        g_perm[sbase[t] + r] = (int)(lo + i);
    }
}

// ---------------------------------------------------------------------------
// Kernel 2: gather-accumulate + FUSED finalize.
//   Warp-per-row over perm (type-sorted), lane l owns channels [4l,4l+4).
//   REGISTER float4 sum/sumsq; atomic flush only at type boundaries.
//   Then grid barrier; first TC global threads finalize mean/rstd and
//   RE-ZERO g_sum/g_sum2/g_typecnt for the next replay.
//   __launch_bounds__(256,3) guarantees all 444 blocks co-resident.
// ---------------------------------------------------------------------------
#define CW 8
__global__ void __launch_bounds__(256, 3) k_gather(
    const float* __restrict__ x, long long N)
{
    __shared__ int st[TT + 1];
    const int tid  = threadIdx.x;
    const int lane = tid & 31;
    for (int i = tid; i < TT + 1; i += 256) st[i] = g_typestart[i];
    __syncthreads();

    const long long nwarps = (long long)GH * 8;
    const long long gw  = (long long)blockIdx.x * 8 + (tid >> 5);
    const long long per = (N + nwarps - 1) / nwarps;
    const long long a = gw * per;
    const long long b = (a + per < N) ? a + per : N;

    if (a < b) {   // NO early return: every thread must reach the barrier
        int t = 0;
        while (st[t + 1] <= (int)a) t++;
        int nxt = st[t + 1];

        float4 s = make_float4(0.f, 0.f, 0.f, 0.f);
        float4 q = make_float4(0.f, 0.f, 0.f, 0.f);
        const float4* __restrict__ x4 = (const float4*)x;

#define FLUSH() do {                                                      \
        if (q.x + q.y + q.z + q.w != 0.f) {                               \
            int base_ = t * CC + 4 * lane;                                \
            atomicAdd(&g_sum[base_ + 0], s.x);                            \
            atomicAdd(&g_sum[base_ + 1], s.y);                            \
            atomicAdd(&g_sum[base_ + 2], s.z);                            \
            atomicAdd(&g_sum[base_ + 3], s.w);                            \
            atomicAdd(&g_sum2[base_ + 0], q.x);                           \
            atomicAdd(&g_sum2[base_ + 1], q.y);                           \
            atomicAdd(&g_sum2[base_ + 2], q.z);                           \
            atomicAdd(&g_sum2[base_ + 3], q.w);                           \
            s = make_float4(0.f, 0.f, 0.f, 0.f);                          \
            q = make_float4(0.f, 0.f, 0.f, 0.f);                          \
        }                                                                  \
    } while (0)

        int rrA[CW];
        #pragma unroll
        for (int u = 0; u < CW; u++)
            rrA[u] = (a + u < b) ? g_perm[a + u] : 0;

        for (long long i = a; i < b; i += CW) {
            int rrB[CW];
            const long long i2 = i + CW;
            #pragma unroll
            for (int u = 0; u < CW; u++)
                rrB[u] = (i2 + u < b) ? g_perm[i2 + u] : 0;

            const int m = (int)((b - i < CW) ? (b - i) : CW);
            float4 xv[CW];
            #pragma unroll
            for (int u = 0; u < CW; u++)
                if (u < m) xv[u] = x4[(long long)rrA[u] * (CC / 4) + lane];

            #pragma unroll
            for (int u = 0; u < CW; u++) {
                if (u < m) {
                    const int idx = (int)(i + u);
                    if (idx >= nxt) {            // type boundary (rare)
                        FLUSH();
                        do { t++; } while (st[t + 1] <= idx);
                        nxt = st[t + 1];
                    }
                    s.x += xv[u].x; s.y += xv[u].y;
                    s.z += xv[u].z; s.w += xv[u].w;
                    q.x = fmaf(xv[u].x, xv[u].x, q.x);
                    q.y = fmaf(xv[u].y, xv[u].y, q.y);
                    q.z = fmaf(xv[u].z, xv[u].z, q.z);
                    q.w = fmaf(xv[u].w, xv[u].w, q.w);
                }
            }
            #pragma unroll
            for (int u = 0; u < CW; u++) rrA[u] = rrB[u];
        }
        FLUSH();
#undef FLUSH
    }

    grid_barrier(tid);   // all g_sum/g_sum2 atomics now visible

    // Finalize: mean / rstd (cnt >= 1, var >= 0, std = sqrt(var+1e-5)).
    // Then re-zero scratch so the next replay starts clean.
    const int e = blockIdx.x * 256 + tid;
    if (e < TC) {
        float cnt  = fmaxf(g_cnt[e >> 7], 1.f);
        float mean = g_sum[e] / cnt;
        float var  = fmaxf(g_sum2[e] / cnt - mean * mean, 0.f);
        g_mean[e] = mean;
        g_rstd[e] = 1.f / sqrtf(var + 1e-5f);
        g_sum[e]  = 0.f;
        g_sum2[e] = 0.f;
    }
    if (e < TT) g_typecnt[e] = 0;
}

// ---------------------------------------------------------------------------
// Kernel 3: normalize (at the HBM cap ~6.3 TB/s; proven design).
// Warp-per-row, float4 loads/stores, stats staged in shared as SEPARATE
// mean/rstd tables (conflict-free LDS.128). blockDim = 512, grid = 444.
// ---------------------------------------------------------------------------
#define NRM_U 4
__global__ void __launch_bounds__(512) k_norm(
    const float* __restrict__ x, const void* __restrict__ tv,
    float* __restrict__ out, long long N)
{
    extern __shared__ float smn[];
    float* smean = smn;        // TC
    float* srstd = smn + TC;   // TC
    const int tid = threadIdx.x;

    #pragma unroll
    for (int i = tid; i < TC; i += 512) {
        smean[i] = g_mean[i];
        srstd[i] = g_rstd[i];
    }
    __syncthreads();

    const int is64 = g_is64;
    const long long* __restrict__ tv64 = (const long long*)tv;
    const int*       __restrict__ tv32 = (const int*)tv;

    const int lane = tid & 31;
    const long long w  = (long long)blockIdx.x * 16 + (tid >> 5);
    const long long nw = (long long)gridDim.x * 16;
    const float4* __restrict__ x4 = (const float4*)x;
    float4* __restrict__ o4 = (float4*)out;

    for (long long r0 = w * NRM_U; r0 < N; r0 += nw * NRM_U) {
        float4 xv[NRM_U];
        int    ty[NRM_U];

        #pragma unroll
        for (int u = 0; u < NRM_U; u++) {
            long long r = r0 + u;
            if (r < N) {
                ty[u] = is64 ? (int)tv64[r] : tv32[r];
                xv[u] = x4[r * (CC / 4) + lane];
            } else ty[u] = -1;
        }
        #pragma unroll
        for (int u = 0; u < NRM_U; u++) {
            if (ty[u] >= 0) {
                int o = ty[u] * CC + 4 * lane;
                float4 mn = *(const float4*)&smean[o];
                float4 rs = *(const float4*)&srstd[o];
                float4 res;
                res.x = (xv[u].x - mn.x) * rs.x;
                res.y = (xv[u].y - mn.y) * rs.y;
                res.z = (xv[u].z - mn.z) * rs.z;
                res.w = (xv[u].w - mn.w) * rs.w;
                o4[(r0 + u) * (CC / 4) + lane] = res;
            }
        }
    }
}

// ---------------------------------------------------------------------------
// Launch — 3 kernels total.
// ---------------------------------------------------------------------------
extern "C" void kernel_launch(void* const* d_in, const int* in_sizes, int n_in,
                              void* d_out, int out_size)
{
    const float* x  = (const float*)d_in[0];
    const void*  tv = d_in[1];
    float* out = (float*)d_out;
    const long long N = (long long)in_sizes[1];   // rows (type_vec length)

    const long long chunk = (N + GH - 1) / GH;
    const int SORT_SMEM = (int)(chunk * sizeof(int));   // tv cache (~9 KB @ N=1e6)
    const int NRM_SMEM  = 2 * TC * (int)sizeof(float);  // 64 KB

    cudaFuncSetAttribute(k_sort, cudaFuncAttributeMaxDynamicSharedMemorySize, SORT_SMEM);
    cudaFuncSetAttribute(k_norm, cudaFuncAttributeMaxDynamicSharedMemorySize, NRM_SMEM);

    k_sort  <<<GH, STB, SORT_SMEM>>>(tv, N);
    k_gather<<<GH, 256>>>(x, N);
    k_norm  <<<444, 512, NRM_SMEM>>>(x, tv, out, N);
}